// round 14
// baseline (speedup 1.0000x reference)
#include <cuda_runtime.h>
#include <cuda_fp16.h>

// ---------------- problem constants ----------------
constexpr int B    = 4;
constexpr int CIN  = 32;
constexpr int NN   = 1024;
constexpr int SS   = 32;
constexpr int COUT = 64;
constexpr int CSP  = 64;
constexpr int EE   = 16384;
constexpr int BN_PART = 64;
constexpr float EPSV = 1e-5f;
constexpr float INV_CNT = 1.f / (float)(B * NN * SS);

// ---------------- device scratch ----------------
__device__ __half g_ht [B*NN*SS*COUT];   // conv1 raw fp16 [b][n][s][c]
__device__ __half g_hwh[B*NN*SS*CSP];    // projection [b][n][s][d] fp16 (node-major)
__device__ float  g_agg[B*NN*SS*CSP];    // gcn agg [b][n][s][d] (node-major)
__device__ __half g_h2t[B*NN*SS*COUT];   // conv2 raw fp16 [b][n][s][c]

__device__ __half g_W1h[64*96];          // [c][tap*32+cin]
__device__ __half g_W2h[64*192];         // [c][tap*64+cin]
__device__ __half g_Wgh[64*64];          // Wg^T [d][c]

__device__ int   g_is64;
__device__ int   g_deg[NN];
__device__ int   g_fill[NN];
__device__ int   g_rowptr[NN+1];
__device__ int   g_col[EE];
__device__ float g_wgt[EE];
__device__ float g_dinv[NN];

__device__ float g_bn1p[2*BN_PART*COUT];
__device__ float g_bn2p[2*BN_PART*COUT];
__device__ float g_bnssum[B*SS*CSP];
__device__ float g_bnssq [B*SS*CSP];

// ---------------- mma helpers ----------------
__device__ __forceinline__ unsigned su32(const void* p) {
    return (unsigned)__cvta_generic_to_shared(p);
}
__device__ __forceinline__ void ldmA(unsigned addr, unsigned& a0, unsigned& a1,
                                     unsigned& a2, unsigned& a3) {
    asm volatile("ldmatrix.sync.aligned.m8n8.x4.shared.b16 {%0,%1,%2,%3}, [%4];"
                 : "=r"(a0), "=r"(a1), "=r"(a2), "=r"(a3) : "r"(addr));
}
__device__ __forceinline__ void ldmB(unsigned addr, unsigned& b0, unsigned& b1) {
    asm volatile("ldmatrix.sync.aligned.m8n8.x2.shared.b16 {%0,%1}, [%2];"
                 : "=r"(b0), "=r"(b1) : "r"(addr));
}
__device__ __forceinline__ void mma16816(float* c, unsigned a0, unsigned a1,
                                         unsigned a2, unsigned a3,
                                         unsigned b0, unsigned b1) {
    asm volatile("mma.sync.aligned.m16n8k16.row.col.f32.f16.f16.f32 "
                 "{%0,%1,%2,%3},{%4,%5,%6,%7},{%8,%9},{%0,%1,%2,%3};"
                 : "+f"(c[0]), "+f"(c[1]), "+f"(c[2]), "+f"(c[3])
                 : "r"(a0), "r"(a1), "r"(a2), "r"(a3), "r"(b0), "r"(b1));
}

// ---------------- prep: detect dtype + zero + weight convert/relayout ----------------
__global__ void k_prep(const int* __restrict__ w, const float* __restrict__ W1,
                       const float* __restrict__ W2, const float* __restrict__ Wg) {
    int t = threadIdx.x;
    int gid = blockIdx.x * 256 + t;
    if (blockIdx.x == 0) {
        __shared__ int s_any;
        if (t == 0) s_any = 0;
        __syncthreads();
        if (w[2 * (t * 64) + 1] != 0) atomicOr(&s_any, 1);
        __syncthreads();
        if (t == 0) g_is64 = s_any ? 0 : 1;
    }
    if (gid < NN) { g_deg[gid] = 0; g_fill[gid] = 0; }
    if (gid < 2*BN_PART*COUT) { g_bn1p[gid] = 0.f; g_bn2p[gid] = 0.f; }
    if (gid < B*SS*CSP) { g_bnssum[gid] = 0.f; g_bnssq[gid] = 0.f; }
    if (gid < 64*96) {
        int c = gid / 96, r = gid % 96, tap = r >> 5, cin = r & 31;
        g_W1h[gid] = __float2half(W1[c * 96 + cin * 3 + tap]);
    }
    if (gid < 64*192) {
        int c = gid / 192, r = gid % 192, tap = r >> 6, cin = r & 63;
        g_W2h[gid] = __float2half(W2[c * 192 + cin * 3 + tap]);
    }
    if (gid < 64*64)
        g_Wgh[gid] = __float2half(Wg[(gid & 63) * 64 + (gid >> 6)]);
}

// ---------------- scan (between conv1m and hwm) ----------------
__global__ void k_scan() {
    int t = threadIdx.x, lane = t & 31, wid = t >> 5;
    int c = g_deg[t];
    g_dinv[t] = rsqrtf((float)(c + 1));
    int v = c;
#pragma unroll
    for (int o = 1; o < 32; o <<= 1) {
        int u = __shfl_up_sync(0xffffffffu, v, o);
        if (lane >= o) v += u;
    }
    __shared__ int wsum[32];
    if (lane == 31) wsum[wid] = v;
    __syncthreads();
    if (wid == 0) {
        int wv = wsum[lane];
#pragma unroll
        for (int o = 1; o < 32; o <<= 1) {
            int u = __shfl_up_sync(0xffffffffu, wv, o);
            if (lane >= o) wv += u;
        }
        wsum[lane] = wv;
    }
    __syncthreads();
    int off = (wid > 0) ? wsum[wid - 1] : 0;
    g_rowptr[t + 1] = off + v;
    if (t == 0) g_rowptr[0] = 0;
}

// ========== tapped tensor-core conv core ==========
template<int CINT, int LDX, int LDB>
__device__ __forceinline__ void conv_tap_mma(const __half* Xs, const __half* Bs,
                                             float* Cs, int t) {
    int wm = t >> 5, lane = t & 31;
    int nd = wm >> 1;
    int sLoc = (wm & 1) * 16 + (lane & 15);
    float acc[8][4];
#pragma unroll
    for (int nt = 0; nt < 8; nt++)
#pragma unroll
        for (int i = 0; i < 4; i++) acc[nt][i] = 0.f;

    unsigned xb = su32(Xs);
    unsigned bb = su32(Bs) + ((lane & 7) * LDB + ((lane >> 3) & 1) * 8) * 2;
#pragma unroll
    for (int tap = 0; tap < 3; tap++) {
        unsigned aBase = xb + ((nd * 34 + sLoc + tap) * LDX + (lane >> 4) * 8) * 2;
#pragma unroll
        for (int kb = 0; kb < CINT / 16; kb++) {
            unsigned a0, a1, a2, a3;
            ldmA(aBase + kb * 32, a0, a1, a2, a3);
            unsigned bOff = (tap * CINT + kb * 16) * 2;
#pragma unroll
            for (int nt = 0; nt < 8; nt++) {
                unsigned b0, b1;
                ldmB(bb + (unsigned)(nt * 8 * LDB) * 2 + bOff, b0, b1);
                mma16816(acc[nt], a0, a1, a2, a3, b0, b1);
            }
        }
    }
#pragma unroll
    for (int nt = 0; nt < 8; nt++) {
        int r0 = wm * 16 + (lane >> 2);
        int col = nt * 8 + (lane & 3) * 2;
        *(float2*)&Cs[r0 * 68 + col]       = make_float2(acc[nt][0], acc[nt][1]);
        *(float2*)&Cs[(r0 + 8) * 68 + col] = make_float2(acc[nt][2], acc[nt][3]);
    }
    __syncthreads();
}

// epilogue: Cs[pos][c]+bias -> fp16 gdst[pos*64+c], BN partials in fp32
__device__ __forceinline__ void conv_epi(const float* Cs, __half* gdst,
                                         const float* __restrict__ bias,
                                         float* part, int slot, int t) {
    int c = t & 63, ndt = t >> 6;
    float bb = bias[c];
    float sm = 0.f, sq = 0.f;
#pragma unroll
    for (int i = 0; i < 32; i++) {
        int pos = i * 4 + ndt;
        float v = Cs[pos * 68 + c] + bb;
        gdst[pos * 64 + c] = __float2half(v);
        sm += v; sq += v * v;
    }
    atomicAdd(&part[slot * 64 + c], sm);
    atomicAdd(&part[BN_PART * 64 + slot * 64 + c], sq);
}

__device__ __forceinline__ void bn_fold(const float* part, const float* __restrict__ g,
                                        const float* __restrict__ be,
                                        float* scs, float* shs, int t) {
    if (t < 64) {
        float sm = 0.f, sq = 0.f;
#pragma unroll 8
        for (int s = 0; s < BN_PART; s++) {
            sm += part[s * 64 + t];
            sq += part[BN_PART * 64 + s * 64 + t];
        }
        float mean = sm * INV_CNT;
        float var  = sq * INV_CNT - mean * mean;
        float sc   = g[t] * rsqrtf(var + EPSV);
        scs[t] = sc;
        shs[t] = be[t] - mean * sc;
    }
}

// ---------------- conv1 (tap-mma) + embedded degree count ----------------
__global__ void __launch_bounds__(256) k_conv1m(const float* __restrict__ x,
                                                const float* __restrict__ b1,
                                                const int* __restrict__ ew) {
    constexpr int LDX = 40, LDB = 104;
    extern __shared__ char dsm[];
    __half* Bs = (__half*)dsm;                     // 13312
    __half* Xs = (__half*)(dsm + 13312);           // 10880
    float*  Cs = (float*)(dsm + 13312 + 10880);    // 34816

    int bid = blockIdx.x;
    int b  = bid >> 8;
    int n0 = (bid & 255) * 4;
    int t  = threadIdx.x;

    // embedded degree count: 16 edges per block
    if (t < 16) {
        int e = bid * 16 + t;
        int stride = g_is64 ? 2 : 1;
        int d = ew[stride * (EE + e)];
        if ((unsigned)d < (unsigned)NN) atomicAdd(&g_deg[d], 1);
    }

    for (int i = t; i < 64 * 48; i += 256) {
        int c = i / 48, o = i % 48;
        *(unsigned*)(Bs + c * LDB + o * 2) = *(const unsigned*)(g_W1h + c * 96 + o * 2);
    }
    if (t < 128) {
        int nd = t >> 5, r = (t >> 4) & 1, cp = t & 15;
        *(__half2*)(Xs + (nd * 34 + r * 33) * LDX + cp * 2) = __half2half2(__float2half(0.f));
    }
    {
        int i = t;
#pragma unroll
        for (int it = 0; it < 2; it++, i += 256) {
            int nd = i >> 7, cp = (i >> 3) & 15, v = i & 7;
            float4 q0 = *(const float4*)(x + (((size_t)b * CIN + 2*cp)     * NN + (n0 + nd)) * SS + v * 4);
            float4 q1 = *(const float4*)(x + (((size_t)b * CIN + 2*cp + 1) * NN + (n0 + nd)) * SS + v * 4);
            __half* dst = Xs + (nd * 34 + 1 + v * 4) * LDX + cp * 2;
            *(__half2*)(dst)           = __floats2half2_rn(q0.x, q1.x);
            *(__half2*)(dst + LDX)     = __floats2half2_rn(q0.y, q1.y);
            *(__half2*)(dst + 2 * LDX) = __floats2half2_rn(q0.z, q1.z);
            *(__half2*)(dst + 3 * LDX) = __floats2half2_rn(q0.w, q1.w);
        }
    }
    __syncthreads();
    conv_tap_mma<32, LDX, LDB>(Xs, Bs, Cs, t);
    __half* gdst = g_ht + ((size_t)b * NN + n0) * SS * 64;
    conv_epi(Cs, gdst, b1, g_bn1p, bid & (BN_PART - 1), t);
}

// ---------------- hw (mma, folded BN1) + embedded CSR fill ----------------
__global__ void __launch_bounds__(256) k_hwm(const float* __restrict__ g1,
                                             const float* __restrict__ be1,
                                             const int* __restrict__ ew) {
    constexpr int LD = 72;
    extern __shared__ char dsm[];
    __half* Bs = (__half*)dsm;                  // 9216
    __half* As = (__half*)(dsm + 9216);         // 18432 (union with Cs 34816)
    float*  Cs = (float*)(dsm + 9216);
    float*  scs = (float*)(dsm + 9216 + 34816);
    float*  shs = scs + 64;

    int bid = blockIdx.x;
    int b  = bid >> 8;
    int n0 = (bid & 255) * 4;
    int t  = threadIdx.x;

    // embedded CSR fill: 16 edges per block
    if (t < 16) {
        int e = bid * 16 + t;
        int stride = g_is64 ? 2 : 1;
        int s = ew[stride * e];
        int d = ew[stride * (EE + e)];
        if ((unsigned)s < (unsigned)NN && (unsigned)d < (unsigned)NN) {
            int pos = atomicAdd(&g_fill[d], 1);
            int j = g_rowptr[d] + pos;
            g_col[j] = s;
            g_wgt[j] = g_dinv[s] * g_dinv[d];
        }
    }

    bn_fold(g_bn1p, g1, be1, scs, shs, t);
    for (int i = t; i < 64 * 32; i += 256) {
        int c = i / 32, o = i % 32;
        *(unsigned*)(Bs + c * LD + o * 2) = *(const unsigned*)(g_Wgh + c * 64 + o * 2);
    }
    __syncthreads();
    const __half* gsrc = g_ht + ((size_t)b * NN + n0) * SS * 64;
#pragma unroll
    for (int it = 0; it < 16; it++) {
        int i = it * 256 + t;
        int pos = i >> 5, dp = i & 31;
        float2 v = __half22float2(*(const __half2*)(gsrc + pos * 64 + dp * 2));
        float a  = fmaxf(fmaf(v.x, scs[dp*2],   shs[dp*2]),   0.f);
        float bv = fmaxf(fmaf(v.y, scs[dp*2+1], shs[dp*2+1]), 0.f);
        *(__half2*)(As + pos * LD + dp * 2) = __floats2half2_rn(a, bv);
    }
    __syncthreads();
    {
        int wm = t >> 5, lane = t & 31;
        float acc[8][4];
#pragma unroll
        for (int nt = 0; nt < 8; nt++)
#pragma unroll
            for (int i = 0; i < 4; i++) acc[nt][i] = 0.f;
        unsigned aBase = su32(As) + ((wm * 16 + (lane & 15)) * LD + (lane >> 4) * 8) * 2;
        unsigned bBase = su32(Bs) + ((lane & 7) * LD + ((lane >> 3) & 1) * 8) * 2;
#pragma unroll
        for (int kb = 0; kb < 4; kb++) {
            unsigned a0, a1, a2, a3;
            ldmA(aBase + kb * 32, a0, a1, a2, a3);
#pragma unroll
            for (int nt = 0; nt < 8; nt++) {
                unsigned b0, b1;
                ldmB(bBase + (unsigned)(nt * 8 * LD) * 2 + kb * 32, b0, b1);
                mma16816(acc[nt], a0, a1, a2, a3, b0, b1);
            }
        }
        __syncthreads();
#pragma unroll
        for (int nt = 0; nt < 8; nt++) {
            int r0 = wm * 16 + (lane >> 2);
            int col = nt * 8 + (lane & 3) * 2;
            *(float2*)&Cs[r0 * 68 + col]       = make_float2(acc[nt][0], acc[nt][1]);
            *(float2*)&Cs[(r0 + 8) * 68 + col] = make_float2(acc[nt][2], acc[nt][3]);
        }
        __syncthreads();
    }
    __half* gdst = g_hwh + ((size_t)b * NN + n0) * SS * 64;
#pragma unroll
    for (int it = 0; it < 16; it++) {
        int i = it * 256 + t;
        int pos = i >> 5, dp = i & 31;
        float2 f = *(const float2*)&Cs[pos * 68 + dp * 2];
        *(__half2*)(gdst + pos * 64 + dp * 2) = __floats2half2_rn(f.x, f.y);
    }
}

// ---------------- GCN gather: block = (b,n), all 32 timesteps per edge ----------------
__device__ __forceinline__ void acc8(float* acc, uint4 q, float w) {
    __half2* hp = (__half2*)&q;
#pragma unroll
    for (int k = 0; k < 4; k++) {
        float2 f = __half22float2(hp[k]);
        acc[2*k]   = fmaf(f.x, w, acc[2*k]);
        acc[2*k+1] = fmaf(f.y, w, acc[2*k+1]);
    }
}
__global__ void __launch_bounds__(256) k_gather(const float* __restrict__ bg) {
    int bid = blockIdx.x;                 // b*NN + n
    int b = bid >> 10, n = bid & 1023;
    int t = threadIdx.x;
    int o = t * 8;

    const __half* base = g_hwh + (size_t)b * NN * 2048;
    float di = g_dinv[n];
    float sl = di * di;
    float acc[8];
#pragma unroll
    for (int k = 0; k < 8; k++) acc[k] = 0.f;
    {
        uint4 q = *(const uint4*)(base + (size_t)n * 2048 + o);
        acc8(acc, q, sl);
    }
    int jb = g_rowptr[n], je = g_rowptr[n + 1];
    int j = jb;
    for (; j + 4 <= je; j += 4) {
        int   c0 = g_col[j],   c1 = g_col[j+1], c2 = g_col[j+2], c3 = g_col[j+3];
        float w0 = g_wgt[j],   w1 = g_wgt[j+1], w2 = g_wgt[j+2], w3 = g_wgt[j+3];
        uint4 q0 = *(const uint4*)(base + (size_t)c0 * 2048 + o);
        uint4 q1 = *(const uint4*)(base + (size_t)c1 * 2048 + o);
        uint4 q2 = *(const uint4*)(base + (size_t)c2 * 2048 + o);
        uint4 q3 = *(const uint4*)(base + (size_t)c3 * 2048 + o);
        acc8(acc, q0, w0); acc8(acc, q1, w1); acc8(acc, q2, w2); acc8(acc, q3, w3);
    }
    for (; j < je; j++) {
        uint4 q = *(const uint4*)(base + (size_t)g_col[j] * 2048 + o);
        acc8(acc, q, g_wgt[j]);
    }
    int dbase = o & 63;
#pragma unroll
    for (int k = 0; k < 8; k++) acc[k] += bg[dbase + k];
    float4* dst = (float4*)(g_agg + (size_t)bid * 2048 + o);
    dst[0] = make_float4(acc[0], acc[1], acc[2], acc[3]);
    dst[1] = make_float4(acc[4], acc[5], acc[6], acc[7]);
}

// ---------------- BN_s stats over nodes ----------------
__global__ void __launch_bounds__(256) k_stats() {
    int bid = blockIdx.x;                 // b(4) x s(32) x q(4)
    int b = bid >> 7, s = (bid >> 2) & 31, q = bid & 3;
    int t = threadIdx.x;
    int d = t & 63, ng = t >> 6;
    float sm = 0.f, sq = 0.f;
    const float* base = g_agg + ((size_t)b * NN + q * 256) * 2048 + s * 64 + d;
#pragma unroll 8
    for (int i = 0; i < 64; i++) {
        float v = base[(size_t)(i * 4 + ng) * 2048];
        sm += v; sq += v * v;
    }
    __shared__ float r1[256], r2[256];
    r1[t] = sm; r2[t] = sq;
    __syncthreads();
    if (t < 64) {
        float s1 = r1[t] + r1[t+64] + r1[t+128] + r1[t+192];
        float s2 = r2[t] + r2[t+64] + r2[t+128] + r2[t+192];
        atomicAdd(&g_bnssum[(b * SS + s) * 64 + t], s1);
        atomicAdd(&g_bnssq [(b * SS + s) * 64 + t], s2);
    }
}

// ---------------- conv2 (tap-mma, folded BN_s): -> g_h2t fp16 + BN2 partials ----------
__global__ void __launch_bounds__(256) k_conv2m(const float* __restrict__ b2,
                                                const float* __restrict__ gs,
                                                const float* __restrict__ bes) {
    constexpr int LDX = 72, LDB = 200;
    extern __shared__ char dsm[];
    __half* Bs = (__half*)dsm;                     // 25600
    __half* Xs = (__half*)(dsm + 25600);           // 19584
    float*  Cs = (float*)(dsm + 25600 + 19584);    // 34816
    float*  scs = (float*)(dsm + 25600 + 19584 + 34816);  // 8192
    float*  shs = scs + 2048;                               // 8192

    int bid = blockIdx.x;
    int b  = bid >> 8;
    int n0 = (bid & 255) * 4;
    int t  = threadIdx.x;

#pragma unroll
    for (int it = 0; it < 8; it++) {
        int i = it * 256 + t;
        int sl = i >> 6, dch = i & 63;
        int bsi = b * SS + sl;
        float mean = g_bnssum[bsi * 64 + dch] * (1.f / NN);
        float var  = g_bnssq [bsi * 64 + dch] * (1.f / NN) - mean * mean;
        float sc   = gs[dch] * rsqrtf(var + EPSV);
        scs[i] = sc;
        shs[i] = bes[dch] - mean * sc;
    }
    for (int i = t; i < 64 * 96; i += 256) {
        int c = i / 96, o = i % 96;
        *(unsigned*)(Bs + c * LDB + o * 2) = *(const unsigned*)(g_W2h + c * 192 + o * 2);
    }
    if (t < 256) {
        int nd = t >> 6, r = (t >> 5) & 1, cp = t & 31;
        *(__half2*)(Xs + (nd * 34 + r * 33) * LDX + cp * 2) = __half2half2(__float2half(0.f));
    }
    __syncthreads();
    const float* asrc = g_agg + ((size_t)b * NN + n0) * 2048;
#pragma unroll
    for (int it = 0; it < 16; it++) {
        int i = it * 256 + t;
        int nd = i >> 10, sidx = (i >> 5) & 31, dp = i & 31;
        float2 v  = *(const float2*)(asrc + (size_t)(nd * 32 + sidx) * 64 + dp * 2);
        float2 sc = *(const float2*)(scs + sidx * 64 + dp * 2);
        float2 sh = *(const float2*)(shs + sidx * 64 + dp * 2);
        float a  = fmaxf(fmaf(v.x, sc.x, sh.x), 0.f);
        float bv = fmaxf(fmaf(v.y, sc.y, sh.y), 0.f);
        *(__half2*)(Xs + (nd * 34 + 1 + sidx) * LDX + dp * 2) = __floats2half2_rn(a, bv);
    }
    __syncthreads();
    conv_tap_mma<64, LDX, LDB>(Xs, Bs, Cs, t);
    __half* gdst = g_h2t + ((size_t)b * NN + n0) * SS * 64;
    conv_epi(Cs, gdst, b2, g_bn2p, bid & (BN_PART - 1), t);
}

// ---------------- output (folded BN2): relu( relu(bn2(h2)) + res ) ----------------
__global__ void __launch_bounds__(256) k_out(const float* __restrict__ x,
                                             const float* __restrict__ Wres,
                                             const float* __restrict__ bres,
                                             const float* __restrict__ g2,
                                             const float* __restrict__ be2,
                                             float* __restrict__ out) {
    extern __shared__ char dsm[];
    float* wrs = (float*)dsm;               // 2048
    float* xs  = wrs + 2048;                // 4096
    float* h2s = xs + 4096;                 // 128*68
    float* scs = h2s + 128 * 68;            // 64
    float* shs = scs + 64;                  // 64

    int bid = blockIdx.x;
    int b  = bid >> 8;
    int n0 = (bid & 255) * 4;
    int t  = threadIdx.x;

    bn_fold(g_bn2p, g2, be2, scs, shs, t);
    for (int i = t; i < 2048; i += 256) {
        int c = i >> 5, cin = i & 31;
        wrs[cin * 64 + c] = Wres[i];
    }
    for (int i = t; i < 1024; i += 256) {
        int nd = i >> 8, cin = (i >> 3) & 31, v = i & 7;
        float4 q = *(const float4*)(x + (((size_t)b * CIN + cin) * NN + (n0 + nd)) * SS + v * 4);
        *(float4*)(xs + (nd * 32 + cin) * 32 + v * 4) = q;
    }
    const __half* gsrc = g_h2t + ((size_t)b * NN + n0) * SS * 64;
#pragma unroll
    for (int i = 0; i < 16; i++) {
        int idx = i * 256 + t;               // half2 index
        float2 f = __half22float2(*(const __half2*)(gsrc + idx * 2));
        int pos = (idx * 2) >> 6, cp = (idx * 2) & 63;
        h2s[pos * 68 + cp]     = f.x;
        h2s[pos * 68 + cp + 1] = f.y;
    }
    __syncthreads();

    int node = t >> 6, cg = (t >> 2) & 15, sq = t & 3;
    int c0 = cg * 4, s0 = sq * 8;
    float acc[4][8];
#pragma unroll
    for (int a = 0; a < 4; a++)
#pragma unroll
        for (int i = 0; i < 8; i++) acc[a][i] = 0.f;

    const float* xbase = xs + node * 32 * 32;
    for (int cin = 0; cin < CIN; cin++) {
        float4 w4 = *(float4*)(wrs + cin * 64 + c0);
        const float* xr = xbase + cin * 32 + s0;
        float4 x0 = *(const float4*)(xr);
        float4 x1 = *(const float4*)(xr + 4);
        float xv[8] = {x0.x, x0.y, x0.z, x0.w, x1.x, x1.y, x1.z, x1.w};
        float wv[4] = {w4.x, w4.y, w4.z, w4.w};
#pragma unroll
        for (int cc = 0; cc < 4; cc++)
#pragma unroll
            for (int i = 0; i < 8; i++)
                acc[cc][i] = fmaf(wv[cc], xv[i], acc[cc][i]);
    }

    int n = n0 + node;
#pragma unroll
    for (int cc = 0; cc < 4; cc++) {
        int c = c0 + cc;
        float sc = scs[c], sh = shs[c], br = bres[c];
        float o[8];
#pragma unroll
        for (int i = 0; i < 8; i++) {
            float hraw = h2s[(node * 32 + s0 + i) * 68 + c];
            float hv = fmaxf(fmaf(hraw, sc, sh), 0.f);
            o[i] = fmaxf(hv + acc[cc][i] + br, 0.f);
        }
        float* dst = out + (((size_t)b * COUT + c) * NN + n) * SS + s0;
        *(float4*)(dst)     = make_float4(o[0], o[1], o[2], o[3]);
        *(float4*)(dst + 4) = make_float4(o[4], o[5], o[6], o[7]);
    }
}

// ---------------- launch (linear, single stream) ----------------
extern "C" void kernel_launch(void* const* d_in, const int* in_sizes, int n_in,
                              void* d_out, int out_size) {
    const float* x    = (const float*)d_in[0];
    const int*   eiw  = (const int*)d_in[1];
    const float* W1   = (const float*)d_in[2];
    const float* b1   = (const float*)d_in[3];
    const float* g1   = (const float*)d_in[4];
    const float* be1  = (const float*)d_in[5];
    const float* Wg   = (const float*)d_in[6];
    const float* bg   = (const float*)d_in[7];
    const float* gs   = (const float*)d_in[8];
    const float* bes  = (const float*)d_in[9];
    const float* W2   = (const float*)d_in[10];
    const float* b2   = (const float*)d_in[11];
    const float* g2   = (const float*)d_in[12];
    const float* be2  = (const float*)d_in[13];
    const float* Wres = (const float*)d_in[14];
    const float* bres = (const float*)d_in[15];
    float*       out  = (float*)d_out;

    const int SM_C1 = 13312 + 10880 + 34816;                     // 59008
    const int SM_C2 = 25600 + 19584 + 34816 + 16384;             // 96384
    const int SM_HW = 9216 + 34816 + 512;                        // 44544
    const int SM_OUT = (2048 + 4096 + 128 * 68 + 128) * 4;       // 59904
    cudaFuncSetAttribute(k_conv1m, cudaFuncAttributeMaxDynamicSharedMemorySize, SM_C1);
    cudaFuncSetAttribute(k_conv2m, cudaFuncAttributeMaxDynamicSharedMemorySize, SM_C2);
    cudaFuncSetAttribute(k_out,    cudaFuncAttributeMaxDynamicSharedMemorySize, SM_OUT);

    k_prep<<<48, 256>>>(eiw, W1, W2, Wg);
    k_conv1m<<<B * (NN / 4), 256, SM_C1>>>(x, b1, eiw);
    k_scan<<<1, NN>>>();
    k_hwm<<<B * (NN / 4), 256, SM_HW>>>(g1, be1, eiw);
    k_gather<<<B * NN, 256>>>(bg);
    k_stats<<<B * SS * 4, 256>>>();
    k_conv2m<<<B * (NN / 4), 256, SM_C2>>>(b2, gs, bes);
    k_out<<<B * (NN / 4), 256, SM_OUT>>>(x, Wres, bres, g2, be2, out);
}

// round 17
// speedup vs baseline: 1.0280x; 1.0280x over previous
#include <cuda_runtime.h>
#include <cuda_fp16.h>

// ---------------- problem constants ----------------
constexpr int B    = 4;
constexpr int CIN  = 32;
constexpr int NN   = 1024;
constexpr int SS   = 32;
constexpr int COUT = 64;
constexpr int CSP  = 64;
constexpr int EE   = 16384;
constexpr int BN_PART = 64;
constexpr float EPSV = 1e-5f;
constexpr float INV_CNT = 1.f / (float)(B * NN * SS);

// ---------------- device scratch ----------------
__device__ __half g_ht [B*NN*SS*COUT];   // conv1 raw fp16 [b][n][s][c]
__device__ __half g_hwh[B*NN*SS*CSP];    // projection [b][n][s][d] fp16 (node-major)
__device__ float  g_agg[B*NN*SS*CSP];    // gcn agg [b][n][s][d] (node-major)
__device__ __half g_h2t[B*NN*SS*COUT];   // conv2 raw fp16 [b][n][s][c]

__device__ __half g_W1h[64*96];          // [c][tap*32+cin]
__device__ __half g_W2h[64*192];         // [c][tap*64+cin]
__device__ __half g_Wgh[64*64];          // Wg^T [d][c]

__device__ int   g_is64;
__device__ int   g_deg[NN];
__device__ int   g_fill[NN];
__device__ int   g_rowptr[NN+1];
__device__ int   g_col[EE];
__device__ float g_wgt[EE];
__device__ float g_dinv[NN];

__device__ float g_bn1p[2*BN_PART*COUT];
__device__ float g_bn2p[2*BN_PART*COUT];
__device__ float g_bnssum[B*SS*CSP];
__device__ float g_bnssq [B*SS*CSP];
__device__ float g_sc1[COUT], g_sh1[COUT];
__device__ float g_sc2[COUT], g_sh2[COUT];
__device__ float g_scs[B*SS*CSP], g_shs[B*SS*CSP];

// ---------------- mma helpers ----------------
__device__ __forceinline__ unsigned su32(const void* p) {
    return (unsigned)__cvta_generic_to_shared(p);
}
__device__ __forceinline__ void ldmA(unsigned addr, unsigned& a0, unsigned& a1,
                                     unsigned& a2, unsigned& a3) {
    asm volatile("ldmatrix.sync.aligned.m8n8.x4.shared.b16 {%0,%1,%2,%3}, [%4];"
                 : "=r"(a0), "=r"(a1), "=r"(a2), "=r"(a3) : "r"(addr));
}
__device__ __forceinline__ void ldmB(unsigned addr, unsigned& b0, unsigned& b1) {
    asm volatile("ldmatrix.sync.aligned.m8n8.x2.shared.b16 {%0,%1}, [%2];"
                 : "=r"(b0), "=r"(b1) : "r"(addr));
}
__device__ __forceinline__ void mma16816(float* c, unsigned a0, unsigned a1,
                                         unsigned a2, unsigned a3,
                                         unsigned b0, unsigned b1) {
    asm volatile("mma.sync.aligned.m16n8k16.row.col.f32.f16.f16.f32 "
                 "{%0,%1,%2,%3},{%4,%5,%6,%7},{%8,%9},{%0,%1,%2,%3};"
                 : "+f"(c[0]), "+f"(c[1]), "+f"(c[2]), "+f"(c[3])
                 : "r"(a0), "r"(a1), "r"(a2), "r"(a3), "r"(b0), "r"(b1));
}

// ---------------- prep: detect dtype + zero + weight convert/relayout ----------------
__global__ void k_prep(const int* __restrict__ w, const float* __restrict__ W1,
                       const float* __restrict__ W2, const float* __restrict__ Wg) {
    int t = threadIdx.x;
    int gid = blockIdx.x * 256 + t;
    if (blockIdx.x == 0) {
        __shared__ int s_any;
        if (t == 0) s_any = 0;
        __syncthreads();
        if (w[2 * (t * 64) + 1] != 0) atomicOr(&s_any, 1);
        __syncthreads();
        if (t == 0) g_is64 = s_any ? 0 : 1;
    }
    if (gid < NN) { g_deg[gid] = 0; g_fill[gid] = 0; }
    if (gid < 2*BN_PART*COUT) { g_bn1p[gid] = 0.f; g_bn2p[gid] = 0.f; }
    if (gid < B*SS*CSP) { g_bnssum[gid] = 0.f; g_bnssq[gid] = 0.f; }
    if (gid < 64*96) {
        int c = gid / 96, r = gid % 96, tap = r >> 5, cin = r & 31;
        g_W1h[gid] = __float2half(W1[c * 96 + cin * 3 + tap]);
    }
    if (gid < 64*192) {
        int c = gid / 192, r = gid % 192, tap = r >> 6, cin = r & 63;
        g_W2h[gid] = __float2half(W2[c * 192 + cin * 3 + tap]);
    }
    if (gid < 64*64)
        g_Wgh[gid] = __float2half(Wg[(gid & 63) * 64 + (gid >> 6)]);
}

// ---------------- scan + BN1 finalize (between conv1m and hwm) ----------------
__global__ void k_scan(const float* __restrict__ g1, const float* __restrict__ be1) {
    int t = threadIdx.x, lane = t & 31, wid = t >> 5;
    int c = g_deg[t];
    g_dinv[t] = rsqrtf((float)(c + 1));
    int v = c;
#pragma unroll
    for (int o = 1; o < 32; o <<= 1) {
        int u = __shfl_up_sync(0xffffffffu, v, o);
        if (lane >= o) v += u;
    }
    __shared__ int wsum[32];
    if (lane == 31) wsum[wid] = v;
    __syncthreads();
    if (wid == 0) {
        int wv = wsum[lane];
#pragma unroll
        for (int o = 1; o < 32; o <<= 1) {
            int u = __shfl_up_sync(0xffffffffu, wv, o);
            if (lane >= o) wv += u;
        }
        wsum[lane] = wv;
    }
    __syncthreads();
    int off = (wid > 0) ? wsum[wid - 1] : 0;
    g_rowptr[t + 1] = off + v;
    if (t == 0) g_rowptr[0] = 0;

    // BN1 finalize (64 threads)
    if (t < 64) {
        float sm = 0.f, sq = 0.f;
#pragma unroll 8
        for (int s = 0; s < BN_PART; s++) {
            sm += g_bn1p[s * 64 + t];
            sq += g_bn1p[BN_PART * 64 + s * 64 + t];
        }
        float mean = sm * INV_CNT;
        float var  = sq * INV_CNT - mean * mean;
        float sc   = g1[t] * rsqrtf(var + EPSV);
        g_sc1[t] = sc;
        g_sh1[t] = be1[t] - mean * sc;
    }
}

// ---------------- BN_s finalize (once, 8192 threads) ----------------
__global__ void k_bnsfin(const float* __restrict__ gs, const float* __restrict__ bes) {
    int i = blockIdx.x * 256 + threadIdx.x;
    if (i >= B * SS * CSP) return;
    int d = i & 63;
    float mean = g_bnssum[i] * (1.f / NN);
    float var  = g_bnssq[i] * (1.f / NN) - mean * mean;
    float sc   = gs[d] * rsqrtf(var + EPSV);
    g_scs[i] = sc;
    g_shs[i] = bes[d] - mean * sc;
}

// ---------------- BN2 finalize (once, 1 block) ----------------
__global__ void k_bnf2(const float* __restrict__ g2, const float* __restrict__ be2) {
    int t = threadIdx.x;   // 64
    float sm = 0.f, sq = 0.f;
#pragma unroll 8
    for (int s = 0; s < BN_PART; s++) {
        sm += g_bn2p[s * 64 + t];
        sq += g_bn2p[BN_PART * 64 + s * 64 + t];
    }
    float mean = sm * INV_CNT;
    float var  = sq * INV_CNT - mean * mean;
    float sc   = g2[t] * rsqrtf(var + EPSV);
    g_sc2[t] = sc;
    g_sh2[t] = be2[t] - mean * sc;
}

// ========== tapped tensor-core conv core ==========
template<int CINT, int LDX, int LDB>
__device__ __forceinline__ void conv_tap_mma(const __half* Xs, const __half* Bs,
                                             float* Cs, int t) {
    int wm = t >> 5, lane = t & 31;
    int nd = wm >> 1;
    int sLoc = (wm & 1) * 16 + (lane & 15);
    float acc[8][4];
#pragma unroll
    for (int nt = 0; nt < 8; nt++)
#pragma unroll
        for (int i = 0; i < 4; i++) acc[nt][i] = 0.f;

    unsigned xb = su32(Xs);
    unsigned bb = su32(Bs) + ((lane & 7) * LDB + ((lane >> 3) & 1) * 8) * 2;
#pragma unroll
    for (int tap = 0; tap < 3; tap++) {
        unsigned aBase = xb + ((nd * 34 + sLoc + tap) * LDX + (lane >> 4) * 8) * 2;
#pragma unroll
        for (int kb = 0; kb < CINT / 16; kb++) {
            unsigned a0, a1, a2, a3;
            ldmA(aBase + kb * 32, a0, a1, a2, a3);
            unsigned bOff = (tap * CINT + kb * 16) * 2;
#pragma unroll
            for (int nt = 0; nt < 8; nt++) {
                unsigned b0, b1;
                ldmB(bb + (unsigned)(nt * 8 * LDB) * 2 + bOff, b0, b1);
                mma16816(acc[nt], a0, a1, a2, a3, b0, b1);
            }
        }
    }
#pragma unroll
    for (int nt = 0; nt < 8; nt++) {
        int r0 = wm * 16 + (lane >> 2);
        int col = nt * 8 + (lane & 3) * 2;
        *(float2*)&Cs[r0 * 68 + col]       = make_float2(acc[nt][0], acc[nt][1]);
        *(float2*)&Cs[(r0 + 8) * 68 + col] = make_float2(acc[nt][2], acc[nt][3]);
    }
    __syncthreads();
}

// epilogue: Cs[pos][c]+bias -> fp16 gdst[pos*64+c], BN partials in fp32
__device__ __forceinline__ void conv_epi(const float* Cs, __half* gdst,
                                         const float* __restrict__ bias,
                                         float* part, int slot, int t) {
    int c = t & 63, ndt = t >> 6;
    float bb = bias[c];
    float sm = 0.f, sq = 0.f;
#pragma unroll
    for (int i = 0; i < 32; i++) {
        int pos = i * 4 + ndt;
        float v = Cs[pos * 68 + c] + bb;
        gdst[pos * 64 + c] = __float2half(v);
        sm += v; sq += v * v;
    }
    atomicAdd(&part[slot * 64 + c], sm);
    atomicAdd(&part[BN_PART * 64 + slot * 64 + c], sq);
}

// ---------------- conv1 (tap-mma) + embedded degree count ----------------
__global__ void __launch_bounds__(256) k_conv1m(const float* __restrict__ x,
                                                const float* __restrict__ b1,
                                                const int* __restrict__ ew) {
    constexpr int LDX = 40, LDB = 104;
    extern __shared__ char dsm[];
    __half* Bs = (__half*)dsm;                     // 13312
    __half* Xs = (__half*)(dsm + 13312);           // 10880
    float*  Cs = (float*)(dsm + 13312 + 10880);    // 34816

    int bid = blockIdx.x;
    int b  = bid >> 8;
    int n0 = (bid & 255) * 4;
    int t  = threadIdx.x;

    if (t < 16) {
        int e = bid * 16 + t;
        int stride = g_is64 ? 2 : 1;
        int d = ew[stride * (EE + e)];
        if ((unsigned)d < (unsigned)NN) atomicAdd(&g_deg[d], 1);
    }

    for (int i = t; i < 64 * 48; i += 256) {
        int c = i / 48, o = i % 48;
        *(unsigned*)(Bs + c * LDB + o * 2) = *(const unsigned*)(g_W1h + c * 96 + o * 2);
    }
    if (t < 128) {
        int nd = t >> 5, r = (t >> 4) & 1, cp = t & 15;
        *(__half2*)(Xs + (nd * 34 + r * 33) * LDX + cp * 2) = __half2half2(__float2half(0.f));
    }
    {
        int i = t;
#pragma unroll
        for (int it = 0; it < 2; it++, i += 256) {
            int nd = i >> 7, cp = (i >> 3) & 15, v = i & 7;
            float4 q0 = *(const float4*)(x + (((size_t)b * CIN + 2*cp)     * NN + (n0 + nd)) * SS + v * 4);
            float4 q1 = *(const float4*)(x + (((size_t)b * CIN + 2*cp + 1) * NN + (n0 + nd)) * SS + v * 4);
            __half* dst = Xs + (nd * 34 + 1 + v * 4) * LDX + cp * 2;
            *(__half2*)(dst)           = __floats2half2_rn(q0.x, q1.x);
            *(__half2*)(dst + LDX)     = __floats2half2_rn(q0.y, q1.y);
            *(__half2*)(dst + 2 * LDX) = __floats2half2_rn(q0.z, q1.z);
            *(__half2*)(dst + 3 * LDX) = __floats2half2_rn(q0.w, q1.w);
        }
    }
    __syncthreads();
    conv_tap_mma<32, LDX, LDB>(Xs, Bs, Cs, t);
    __half* gdst = g_ht + ((size_t)b * NN + n0) * SS * 64;
    conv_epi(Cs, gdst, b1, g_bn1p, bid & (BN_PART - 1), t);
}

// ---------------- hw (mma, BN1 finals from global) + embedded CSR fill ----------------
__global__ void __launch_bounds__(256) k_hwm(const int* __restrict__ ew) {
    constexpr int LD = 72;
    extern __shared__ char dsm[];
    __half* Bs = (__half*)dsm;                  // 9216
    __half* As = (__half*)(dsm + 9216);         // 18432 (union with Cs 34816)
    float*  Cs = (float*)(dsm + 9216);
    float*  scs = (float*)(dsm + 9216 + 34816);
    float*  shs = scs + 64;

    int bid = blockIdx.x;
    int b  = bid >> 8;
    int n0 = (bid & 255) * 4;
    int t  = threadIdx.x;

    if (t < 16) {
        int e = bid * 16 + t;
        int stride = g_is64 ? 2 : 1;
        int s = ew[stride * e];
        int d = ew[stride * (EE + e)];
        if ((unsigned)s < (unsigned)NN && (unsigned)d < (unsigned)NN) {
            int pos = atomicAdd(&g_fill[d], 1);
            int j = g_rowptr[d] + pos;
            g_col[j] = s;
            g_wgt[j] = g_dinv[s] * g_dinv[d];
        }
    }
    if (t >= 64 && t < 128) { scs[t - 64] = g_sc1[t - 64]; shs[t - 64] = g_sh1[t - 64]; }
    for (int i = t; i < 64 * 32; i += 256) {
        int c = i / 32, o = i % 32;
        *(unsigned*)(Bs + c * LD + o * 2) = *(const unsigned*)(g_Wgh + c * 64 + o * 2);
    }
    __syncthreads();
    const __half* gsrc = g_ht + ((size_t)b * NN + n0) * SS * 64;
#pragma unroll
    for (int it = 0; it < 16; it++) {
        int i = it * 256 + t;
        int pos = i >> 5, dp = i & 31;
        float2 v = __half22float2(*(const __half2*)(gsrc + pos * 64 + dp * 2));
        float a  = fmaxf(fmaf(v.x, scs[dp*2],   shs[dp*2]),   0.f);
        float bv = fmaxf(fmaf(v.y, scs[dp*2+1], shs[dp*2+1]), 0.f);
        *(__half2*)(As + pos * LD + dp * 2) = __floats2half2_rn(a, bv);
    }
    __syncthreads();
    {
        int wm = t >> 5, lane = t & 31;
        float acc[8][4];
#pragma unroll
        for (int nt = 0; nt < 8; nt++)
#pragma unroll
            for (int i = 0; i < 4; i++) acc[nt][i] = 0.f;
        unsigned aBase = su32(As) + ((wm * 16 + (lane & 15)) * LD + (lane >> 4) * 8) * 2;
        unsigned bBase = su32(Bs) + ((lane & 7) * LD + ((lane >> 3) & 1) * 8) * 2;
#pragma unroll
        for (int kb = 0; kb < 4; kb++) {
            unsigned a0, a1, a2, a3;
            ldmA(aBase + kb * 32, a0, a1, a2, a3);
#pragma unroll
            for (int nt = 0; nt < 8; nt++) {
                unsigned b0, b1;
                ldmB(bBase + (unsigned)(nt * 8 * LD) * 2 + kb * 32, b0, b1);
                mma16816(acc[nt], a0, a1, a2, a3, b0, b1);
            }
        }
        __syncthreads();
#pragma unroll
        for (int nt = 0; nt < 8; nt++) {
            int r0 = wm * 16 + (lane >> 2);
            int col = nt * 8 + (lane & 3) * 2;
            *(float2*)&Cs[r0 * 68 + col]       = make_float2(acc[nt][0], acc[nt][1]);
            *(float2*)&Cs[(r0 + 8) * 68 + col] = make_float2(acc[nt][2], acc[nt][3]);
        }
        __syncthreads();
    }
    __half* gdst = g_hwh + ((size_t)b * NN + n0) * SS * 64;
#pragma unroll
    for (int it = 0; it < 16; it++) {
        int i = it * 256 + t;
        int pos = i >> 5, dp = i & 31;
        float2 f = *(const float2*)&Cs[pos * 68 + dp * 2];
        *(__half2*)(gdst + pos * 64 + dp * 2) = __floats2half2_rn(f.x, f.y);
    }
}

// ---------------- GCN gather: block = (b,n), all 32 timesteps per edge ----------------
__device__ __forceinline__ void acc8(float* acc, uint4 q, float w) {
    __half2* hp = (__half2*)&q;
#pragma unroll
    for (int k = 0; k < 4; k++) {
        float2 f = __half22float2(hp[k]);
        acc[2*k]   = fmaf(f.x, w, acc[2*k]);
        acc[2*k+1] = fmaf(f.y, w, acc[2*k+1]);
    }
}
__global__ void __launch_bounds__(256) k_gather(const float* __restrict__ bg) {
    int bid = blockIdx.x;                 // b*NN + n
    int b = bid >> 10, n = bid & 1023;
    int t = threadIdx.x;
    int o = t * 8;

    const __half* base = g_hwh + (size_t)b * NN * 2048;
    float di = g_dinv[n];
    float sl = di * di;
    float acc[8];
#pragma unroll
    for (int k = 0; k < 8; k++) acc[k] = 0.f;
    {
        uint4 q = *(const uint4*)(base + (size_t)n * 2048 + o);
        acc8(acc, q, sl);
    }
    int jb = g_rowptr[n], je = g_rowptr[n + 1];
    int j = jb;
    for (; j + 4 <= je; j += 4) {
        int   c0 = g_col[j],   c1 = g_col[j+1], c2 = g_col[j+2], c3 = g_col[j+3];
        float w0 = g_wgt[j],   w1 = g_wgt[j+1], w2 = g_wgt[j+2], w3 = g_wgt[j+3];
        uint4 q0 = *(const uint4*)(base + (size_t)c0 * 2048 + o);
        uint4 q1 = *(const uint4*)(base + (size_t)c1 * 2048 + o);
        uint4 q2 = *(const uint4*)(base + (size_t)c2 * 2048 + o);
        uint4 q3 = *(const uint4*)(base + (size_t)c3 * 2048 + o);
        acc8(acc, q0, w0); acc8(acc, q1, w1); acc8(acc, q2, w2); acc8(acc, q3, w3);
    }
    for (; j < je; j++) {
        uint4 q = *(const uint4*)(base + (size_t)g_col[j] * 2048 + o);
        acc8(acc, q, g_wgt[j]);
    }
    int dbase = o & 63;
#pragma unroll
    for (int k = 0; k < 8; k++) acc[k] += bg[dbase + k];
    float4* dst = (float4*)(g_agg + (size_t)bid * 2048 + o);
    dst[0] = make_float4(acc[0], acc[1], acc[2], acc[3]);
    dst[1] = make_float4(acc[4], acc[5], acc[6], acc[7]);
}

// ---------------- BN_s stats over nodes ----------------
__global__ void __launch_bounds__(256) k_stats() {
    int bid = blockIdx.x;                 // b(4) x s(32) x q(4)
    int b = bid >> 7, s = (bid >> 2) & 31, q = bid & 3;
    int t = threadIdx.x;
    int d = t & 63, ng = t >> 6;
    float sm = 0.f, sq = 0.f;
    const float* base = g_agg + ((size_t)b * NN + q * 256) * 2048 + s * 64 + d;
#pragma unroll 8
    for (int i = 0; i < 64; i++) {
        float v = base[(size_t)(i * 4 + ng) * 2048];
        sm += v; sq += v * v;
    }
    __shared__ float r1[256], r2[256];
    r1[t] = sm; r2[t] = sq;
    __syncthreads();
    if (t < 64) {
        float s1 = r1[t] + r1[t+64] + r1[t+128] + r1[t+192];
        float s2 = r2[t] + r2[t+64] + r2[t+128] + r2[t+192];
        atomicAdd(&g_bnssum[(b * SS + s) * 64 + t], s1);
        atomicAdd(&g_bnssq [(b * SS + s) * 64 + t], s2);
    }
}

// ---------------- conv2 (tap-mma, BN_s finals from global): -> g_h2t + BN2 partials ---
__global__ void __launch_bounds__(256) k_conv2m(const float* __restrict__ b2) {
    constexpr int LDX = 72, LDB = 200;
    extern __shared__ char dsm[];
    __half* Bs = (__half*)dsm;                     // 25600
    __half* Xs = (__half*)(dsm + 25600);           // 19584
    float*  Cs = (float*)(dsm + 25600 + 19584);    // 34816
    float*  scs = (float*)(dsm + 25600 + 19584 + 34816);  // 8192
    float*  shs = scs + 2048;                               // 8192

    int bid = blockIdx.x;
    int b  = bid >> 8;
    int n0 = (bid & 255) * 4;
    int t  = threadIdx.x;

#pragma unroll
    for (int it = 0; it < 8; it++) {        // plain vector copy of finals
        int i = it * 256 + t;
        scs[i] = g_scs[b * 2048 + i];
        shs[i] = g_shs[b * 2048 + i];
    }
    for (int i = t; i < 64 * 96; i += 256) {
        int c = i / 96, o = i % 96;
        *(unsigned*)(Bs + c * LDB + o * 2) = *(const unsigned*)(g_W2h + c * 192 + o * 2);
    }
    if (t < 256) {
        int nd = t >> 6, r = (t >> 5) & 1, cp = t & 31;
        *(__half2*)(Xs + (nd * 34 + r * 33) * LDX + cp * 2) = __half2half2(__float2half(0.f));
    }
    __syncthreads();
    const float* asrc = g_agg + ((size_t)b * NN + n0) * 2048;
#pragma unroll
    for (int it = 0; it < 16; it++) {
        int i = it * 256 + t;
        int nd = i >> 10, sidx = (i >> 5) & 31, dp = i & 31;
        float2 v  = *(const float2*)(asrc + (size_t)(nd * 32 + sidx) * 64 + dp * 2);
        float2 sc = *(const float2*)(scs + sidx * 64 + dp * 2);
        float2 sh = *(const float2*)(shs + sidx * 64 + dp * 2);
        float a  = fmaxf(fmaf(v.x, sc.x, sh.x), 0.f);
        float bv = fmaxf(fmaf(v.y, sc.y, sh.y), 0.f);
        *(__half2*)(Xs + (nd * 34 + 1 + sidx) * LDX + dp * 2) = __floats2half2_rn(a, bv);
    }
    __syncthreads();
    conv_tap_mma<64, LDX, LDB>(Xs, Bs, Cs, t);
    __half* gdst = g_h2t + ((size_t)b * NN + n0) * SS * 64;
    conv_epi(Cs, gdst, b2, g_bn2p, bid & (BN_PART - 1), t);
}

// ---------------- output (BN2 finals from global): relu( relu(bn2(h2)) + res ) --------
__global__ void __launch_bounds__(256) k_out(const float* __restrict__ x,
                                             const float* __restrict__ Wres,
                                             const float* __restrict__ bres,
                                             float* __restrict__ out) {
    extern __shared__ char dsm[];
    float* wrs = (float*)dsm;               // 2048
    float* xs  = wrs + 2048;                // 4096
    float* h2s = xs + 4096;                 // 128*68
    float* scs = h2s + 128 * 68;            // 64
    float* shs = scs + 64;                  // 64

    int bid = blockIdx.x;
    int b  = bid >> 8;
    int n0 = (bid & 255) * 4;
    int t  = threadIdx.x;

    if (t < 64) { scs[t] = g_sc2[t]; shs[t] = g_sh2[t]; }
    for (int i = t; i < 2048; i += 256) {
        int c = i >> 5, cin = i & 31;
        wrs[cin * 64 + c] = Wres[i];
    }
    for (int i = t; i < 1024; i += 256) {
        int nd = i >> 8, cin = (i >> 3) & 31, v = i & 7;
        float4 q = *(const float4*)(x + (((size_t)b * CIN + cin) * NN + (n0 + nd)) * SS + v * 4);
        *(float4*)(xs + (nd * 32 + cin) * 32 + v * 4) = q;
    }
    const __half* gsrc = g_h2t + ((size_t)b * NN + n0) * SS * 64;
#pragma unroll
    for (int i = 0; i < 16; i++) {
        int idx = i * 256 + t;               // half2 index
        float2 f = __half22float2(*(const __half2*)(gsrc + idx * 2));
        int pos = (idx * 2) >> 6, cp = (idx * 2) & 63;
        h2s[pos * 68 + cp]     = f.x;
        h2s[pos * 68 + cp + 1] = f.y;
    }
    __syncthreads();

    int node = t >> 6, cg = (t >> 2) & 15, sq = t & 3;
    int c0 = cg * 4, s0 = sq * 8;
    float acc[4][8];
#pragma unroll
    for (int a = 0; a < 4; a++)
#pragma unroll
        for (int i = 0; i < 8; i++) acc[a][i] = 0.f;

    const float* xbase = xs + node * 32 * 32;
    for (int cin = 0; cin < CIN; cin++) {
        float4 w4 = *(float4*)(wrs + cin * 64 + c0);
        const float* xr = xbase + cin * 32 + s0;
        float4 x0 = *(const float4*)(xr);
        float4 x1 = *(const float4*)(xr + 4);
        float xv[8] = {x0.x, x0.y, x0.z, x0.w, x1.x, x1.y, x1.z, x1.w};
        float wv[4] = {w4.x, w4.y, w4.z, w4.w};
#pragma unroll
        for (int cc = 0; cc < 4; cc++)
#pragma unroll
            for (int i = 0; i < 8; i++)
                acc[cc][i] = fmaf(wv[cc], xv[i], acc[cc][i]);
    }

    int n = n0 + node;
#pragma unroll
    for (int cc = 0; cc < 4; cc++) {
        int c = c0 + cc;
        float sc = scs[c], sh = shs[c], br = bres[c];
        float o[8];
#pragma unroll
        for (int i = 0; i < 8; i++) {
            float hraw = h2s[(node * 32 + s0 + i) * 68 + c];
            float hv = fmaxf(fmaf(hraw, sc, sh), 0.f);
            o[i] = fmaxf(hv + acc[cc][i] + br, 0.f);
        }
        float* dst = out + (((size_t)b * COUT + c) * NN + n) * SS + s0;
        *(float4*)(dst)     = make_float4(o[0], o[1], o[2], o[3]);
        *(float4*)(dst + 4) = make_float4(o[4], o[5], o[6], o[7]);
    }
}

// ---------------- launch (linear, single stream) ----------------
extern "C" void kernel_launch(void* const* d_in, const int* in_sizes, int n_in,
                              void* d_out, int out_size) {
    const float* x    = (const float*)d_in[0];
    const int*   eiw  = (const int*)d_in[1];
    const float* W1   = (const float*)d_in[2];
    const float* b1   = (const float*)d_in[3];
    const float* g1   = (const float*)d_in[4];
    const float* be1  = (const float*)d_in[5];
    const float* Wg   = (const float*)d_in[6];
    const float* bg   = (const float*)d_in[7];
    const float* gs   = (const float*)d_in[8];
    const float* bes  = (const float*)d_in[9];
    const float* W2   = (const float*)d_in[10];
    const float* b2   = (const float*)d_in[11];
    const float* g2   = (const float*)d_in[12];
    const float* be2  = (const float*)d_in[13];
    const float* Wres = (const float*)d_in[14];
    const float* bres = (const float*)d_in[15];
    float*       out  = (float*)d_out;

    const int SM_C1 = 13312 + 10880 + 34816;                     // 59008
    const int SM_C2 = 25600 + 19584 + 34816 + 16384;             // 96384
    const int SM_HW = 9216 + 34816 + 512;                        // 44544
    const int SM_OUT = (2048 + 4096 + 128 * 68 + 128) * 4;       // 59904
    cudaFuncSetAttribute(k_conv1m, cudaFuncAttributeMaxDynamicSharedMemorySize, SM_C1);
    cudaFuncSetAttribute(k_conv2m, cudaFuncAttributeMaxDynamicSharedMemorySize, SM_C2);
    cudaFuncSetAttribute(k_out,    cudaFuncAttributeMaxDynamicSharedMemorySize, SM_OUT);

    k_prep<<<48, 256>>>(eiw, W1, W2, Wg);
    k_conv1m<<<B * (NN / 4), 256, SM_C1>>>(x, b1, eiw);
    k_scan<<<1, NN>>>(g1, be1);
    k_hwm<<<B * (NN / 4), 256, SM_HW>>>(eiw);
    k_gather<<<B * NN, 256>>>(bg);
    k_stats<<<B * SS * 4, 256>>>();
    k_bnsfin<<<32, 256>>>(gs, bes);
    k_conv2m<<<B * (NN / 4), 256, SM_C2>>>(b2);
    k_bnf2<<<1, 64>>>(g2, be2);
    k_out<<<B * (NN / 4), 256, SM_OUT>>>(x, Wres, bres, out);
}